// round 3
// baseline (speedup 1.0000x reference)
#include <cuda_runtime.h>
#include <cuda_bf16.h>
#include <math.h>

#define NNODES 100000
#define NEDGES 1600000

// Scratch buffers (device globals: no allocation allowed).
static __device__ __align__(16) float g_h[NNODES * 64];    // layer input features
static __device__ __align__(16) float g_t[NNODES * 64];    // h @ W result
static __device__ __align__(16) float g_acc[NNODES * 64];  // aggregation accumulator
static __device__ float g_dinv[NNODES];                    // 1/sqrt(deg)
static __device__ int g_src[NEDGES];                       // normalized int32 src
static __device__ int g_dst[NEDGES];                       // normalized int32 dst
static __device__ int g_is64;                              // edge_index dtype flag

// ---------------------------------------------------------------------------
// Detect edge_index dtype: int64 little-endian values < 2^31 have zero high
// words at every odd 32-bit position; random int32 edge IDs do not.
// ---------------------------------------------------------------------------
__global__ void detect_idx_kernel(const unsigned* __restrict__ w, int* is64) {
    __shared__ int s_bad;
    if (threadIdx.x == 0) s_bad = 0;
    __syncthreads();
    int bad = 0;
    for (int i = threadIdx.x; i < 4096; i += blockDim.x)
        if (w[2 * i + 1] != 0u) bad = 1;
    if (bad) atomicOr(&s_bad, 1);
    __syncthreads();
    if (threadIdx.x == 0) *is64 = s_bad ? 0 : 1;
}

// Normalize indices to int32 (works for either stored dtype).
__global__ void convert_idx_kernel(const void* __restrict__ ei, const int* __restrict__ is64,
                                   int* __restrict__ src, int* __restrict__ dst, int e) {
    int i = blockIdx.x * blockDim.x + threadIdx.x;
    if (i >= e) return;
    if (*is64) {
        const long long* p = (const long long*)ei;
        src[i] = (int)p[i];
        dst[i] = (int)p[e + i];
    } else {
        const int* p = (const int*)ei;
        src[i] = p[i];
        dst[i] = p[e + i];
    }
}

// ---------------------------------------------------------------------------
// Degree / normalization
// ---------------------------------------------------------------------------
__global__ void init_deg_kernel(float* deg, int n) {
    int i = blockIdx.x * blockDim.x + threadIdx.x;
    if (i < n) deg[i] = 1.0f;  // self-loop contributes 1
}

__global__ void count_deg_kernel(const int* __restrict__ dst, float* deg, int e) {
    int i = blockIdx.x * blockDim.x + threadIdx.x;
    if (i < e) atomicAdd(&deg[dst[i]], 1.0f);
}

__global__ void finalize_dinv_kernel(float* deg, int n) {
    int i = blockIdx.x * blockDim.x + threadIdx.x;
    if (i < n) deg[i] = rsqrtf(deg[i]);
}

// ---------------------------------------------------------------------------
// GEMM: Y[M,NC] = X[M,K] @ W[K,NC] (+ bias). Smem-tiled, fp32.
// ---------------------------------------------------------------------------
template <int K, int NC, bool BIAS>
__global__ void gemm_kernel(const float* __restrict__ X, const float* __restrict__ W,
                            const float* __restrict__ bias, float* __restrict__ Y, int M) {
    constexpr int BR = 32;
    constexpr int NCH = NC / 2;
    constexpr int TY = 256 / NCH;
    constexpr int RPT = BR / TY;

    extern __shared__ float sm[];
    float* sW = sm;              // K * NC
    float* sX = sm + K * NC;     // K * (BR+1), layout [k][r]

    int tid = threadIdx.x;
    int base = blockIdx.x * BR;

    for (int i = tid; i < K * NC; i += 256) sW[i] = W[i];
    for (int i = tid; i < BR * K; i += 256) {
        int r = i / K, k = i % K;
        sX[k * (BR + 1) + r] = X[(size_t)(base + r) * K + k];
    }
    __syncthreads();

    int tx = tid % NCH;
    int ty = tid / NCH;

    float acc0[RPT], acc1[RPT];
#pragma unroll
    for (int r = 0; r < RPT; r++) { acc0[r] = 0.f; acc1[r] = 0.f; }

#pragma unroll 4
    for (int k = 0; k < K; k++) {
        float w0 = sW[k * NC + tx];
        float w1 = sW[k * NC + tx + NCH];
#pragma unroll
        for (int r = 0; r < RPT; r++) {
            float xv = sX[k * (BR + 1) + ty + r * TY];
            acc0[r] += xv * w0;
            acc1[r] += xv * w1;
        }
    }

#pragma unroll
    for (int r = 0; r < RPT; r++) {
        int row = base + ty + r * TY;
        float b0 = BIAS ? bias[tx] : 0.f;
        float b1 = BIAS ? bias[tx + NCH] : 0.f;
        Y[(size_t)row * NC + tx] = acc0[r] + b0;
        Y[(size_t)row * NC + tx + NCH] = acc1[r] + b1;
    }
}

// ---------------------------------------------------------------------------
// Self-loop init: acc = t * dinv[i]^2 + bias (float4 vectorized)
// ---------------------------------------------------------------------------
template <int NC>
__global__ void self_init_kernel(const float4* __restrict__ t, const float* __restrict__ dinv,
                                 const float4* __restrict__ b, float4* __restrict__ acc, int n) {
    constexpr int PER = NC / 4;
    int idx = blockIdx.x * blockDim.x + threadIdx.x;
    if (idx >= n * PER) return;
    int i = idx / PER;
    int j = idx - i * PER;
    float di = dinv[i];
    float s = di * di;
    float4 v = t[idx];
    float4 bb = b[j];
    v.x = v.x * s + bb.x;
    v.y = v.y * s + bb.y;
    v.z = v.z * s + bb.z;
    v.w = v.w * s + bb.w;
    acc[idx] = v;
}

// ---------------------------------------------------------------------------
// Edge scatter: acc[dst] += t[src] * dinv[src]*dinv[dst]
//   F4 lanes per edge, one float4 per lane, vector red (no return).
// ---------------------------------------------------------------------------
template <int F4>
__global__ void scatter_kernel(const int* __restrict__ src, const int* __restrict__ dst,
                               const float* __restrict__ dinv, const float4* __restrict__ t,
                               float4* __restrict__ acc, int e) {
    int gid = blockIdx.x * blockDim.x + threadIdx.x;
    int ei = gid / F4;
    int lane = gid & (F4 - 1);
    if (ei >= e) return;
    int s = src[ei];
    int d = dst[ei];
    float w = dinv[s] * dinv[d];
    float4 v = t[(size_t)s * F4 + lane];
    v.x *= w; v.y *= w; v.z *= w; v.w *= w;
    float4* p = acc + (size_t)d * F4 + lane;
    asm volatile("red.global.add.v4.f32 [%0], {%1,%2,%3,%4};"
                 :: "l"(p), "f"(v.x), "f"(v.y), "f"(v.z), "f"(v.w)
                 : "memory");
}

// ---------------------------------------------------------------------------
// ReLU copy: h = relu(acc)
// ---------------------------------------------------------------------------
__global__ void relu_kernel(const float* __restrict__ a, float* __restrict__ h, int n) {
    int i = blockIdx.x * blockDim.x + threadIdx.x;
    if (i < n) h[i] = fmaxf(a[i], 0.f);
}

// ---------------------------------------------------------------------------
// Final L2 row-normalize (32 features per node -> one warp per node)
// ---------------------------------------------------------------------------
__global__ void normalize_kernel(const float* __restrict__ a, float* __restrict__ out, int n) {
    int node = blockIdx.x * 8 + (threadIdx.x >> 5);
    int lane = threadIdx.x & 31;
    if (node >= n) return;
    float v = a[node * 32 + lane];
    float ss = v * v;
#pragma unroll
    for (int o = 16; o; o >>= 1) ss += __shfl_xor_sync(0xffffffffu, ss, o);
    float nrm = sqrtf(ss);
    out[node * 32 + lane] = v / fmaxf(nrm, 1e-12f);
}

// ---------------------------------------------------------------------------
extern "C" void kernel_launch(void* const* d_in, const int* in_sizes, int n_in,
                              void* d_out, int out_size) {
    const float* x = (const float*)d_in[0];
    const void* ei = d_in[1];
    const float* W_pre = (const float*)d_in[2];
    const float* b_pre = (const float*)d_in[3];
    const float* W1 = (const float*)d_in[4];
    const float* b1 = (const float*)d_in[5];
    const float* W2 = (const float*)d_in[6];
    const float* b2 = (const float*)d_in[7];
    const float* W3 = (const float*)d_in[8];
    const float* b3 = (const float*)d_in[9];
    float* out = (float*)d_out;

    const int n = NNODES;
    const int e = NEDGES;

    float *h, *t, *acc, *dinv;
    int *src, *dst, *is64;
    cudaGetSymbolAddress((void**)&h, g_h);
    cudaGetSymbolAddress((void**)&t, g_t);
    cudaGetSymbolAddress((void**)&acc, g_acc);
    cudaGetSymbolAddress((void**)&dinv, g_dinv);
    cudaGetSymbolAddress((void**)&src, g_src);
    cudaGetSymbolAddress((void**)&dst, g_dst);
    cudaGetSymbolAddress((void**)&is64, g_is64);

    // shared mem sizes for gemm variants
    const int smem_pre = (128 * 64 + 128 * 33) * 4;   // 49664 > 48KB default
    const int smem_64 = (64 * 64 + 64 * 33) * 4;
    const int smem_32 = (64 * 32 + 64 * 33) * 4;
    cudaFuncSetAttribute(gemm_kernel<128, 64, true>,
                         cudaFuncAttributeMaxDynamicSharedMemorySize, smem_pre);

    // 0) detect edge_index dtype and normalize to int32
    detect_idx_kernel<<<1, 256>>>((const unsigned*)ei, is64);
    convert_idx_kernel<<<(e + 255) / 256, 256>>>(ei, is64, src, dst, e);

    // 1) degree + dinv
    init_deg_kernel<<<(n + 255) / 256, 256>>>(dinv, n);
    count_deg_kernel<<<(e + 255) / 256, 256>>>(dst, dinv, e);
    finalize_dinv_kernel<<<(n + 255) / 256, 256>>>(dinv, n);

    // 2) h = x @ W_pre + b_pre
    gemm_kernel<128, 64, true><<<n / 32, 256, smem_pre>>>(x, W_pre, b_pre, h, n);

    // 3) layer 1: relu(gcn(h, W1, b1))
    gemm_kernel<64, 64, false><<<n / 32, 256, smem_64>>>(h, W1, nullptr, t, n);
    self_init_kernel<64><<<(n * 16 + 255) / 256, 256>>>((const float4*)t, dinv,
                                                        (const float4*)b1, (float4*)acc, n);
    scatter_kernel<16><<<(e * 16 + 255) / 256, 256>>>(src, dst, dinv, (const float4*)t,
                                                      (float4*)acc, e);
    relu_kernel<<<(n * 64 + 255) / 256, 256>>>(acc, h, n * 64);

    // 4) layer 2: relu(gcn(h, W2, b2))
    gemm_kernel<64, 64, false><<<n / 32, 256, smem_64>>>(h, W2, nullptr, t, n);
    self_init_kernel<64><<<(n * 16 + 255) / 256, 256>>>((const float4*)t, dinv,
                                                        (const float4*)b2, (float4*)acc, n);
    scatter_kernel<16><<<(e * 16 + 255) / 256, 256>>>(src, dst, dinv, (const float4*)t,
                                                      (float4*)acc, e);
    relu_kernel<<<(n * 64 + 255) / 256, 256>>>(acc, h, n * 64);

    // 5) layer 3: gcn(h, W3, b3), Fout = 32
    gemm_kernel<64, 32, false><<<n / 32, 256, smem_32>>>(h, W3, nullptr, t, n);
    self_init_kernel<32><<<(n * 8 + 255) / 256, 256>>>((const float4*)t, dinv,
                                                       (const float4*)b3, (float4*)acc, n);
    scatter_kernel<8><<<(e * 8 + 255) / 256, 256>>>(src, dst, dinv, (const float4*)t,
                                                    (float4*)acc, e);

    // 6) L2 normalize rows -> output
    normalize_kernel<<<(n + 7) / 8, 256>>>(acc, out, n);
}

// round 4
// speedup vs baseline: 1.3225x; 1.3225x over previous
#include <cuda_runtime.h>
#include <cuda_bf16.h>
#include <math.h>

#define NNODES 100000
#define NEDGES 1600000
#define SCAN_BLK 512
#define SCAN_NB ((NNODES + SCAN_BLK - 1) / SCAN_BLK)   // 196

// Scratch (device globals; no allocation allowed)
static __device__ __align__(16) float g_h[NNODES * 64];    // layer input features
static __device__ __align__(16) float g_t[NNODES * 64];    // h @ W result
static __device__ __align__(16) float g_acc[NNODES * 64];  // final-layer accumulator
static __device__ float g_dinv[NNODES];                    // 1/sqrt(deg)
static __device__ int g_src[NEDGES];                       // int32 src
static __device__ int g_dst[NEDGES];                       // int32 dst
static __device__ int g_is64;                              // edge_index dtype flag
static __device__ int g_deg[NNODES];                       // in-degree (no self loop)
static __device__ int g_rowptr[NNODES + 1];                // CSR row offsets (by dst)
static __device__ int g_cursor[NNODES];                    // fill cursors
static __device__ int g_bsum[SCAN_NB];                     // scan block sums
static __device__ int g_csrc[NEDGES];                      // CSR: src per slot
static __device__ float g_cw[NEDGES];                      // CSR: edge weight per slot

// ---------------------------------------------------------------------------
// dtype detect + index normalize (int64 values < 2^31 have zero high words)
// ---------------------------------------------------------------------------
__global__ void detect_idx_kernel(const unsigned* __restrict__ w, int* is64) {
    __shared__ int s_bad;
    if (threadIdx.x == 0) s_bad = 0;
    __syncthreads();
    int bad = 0;
    for (int i = threadIdx.x; i < 4096; i += blockDim.x)
        if (w[2 * i + 1] != 0u) bad = 1;
    if (bad) atomicOr(&s_bad, 1);
    __syncthreads();
    if (threadIdx.x == 0) *is64 = s_bad ? 0 : 1;
}

__global__ void convert_idx_kernel(const void* __restrict__ ei, const int* __restrict__ is64,
                                   int* __restrict__ src, int* __restrict__ dst, int e) {
    int i = blockIdx.x * blockDim.x + threadIdx.x;
    if (i >= e) return;
    if (*is64) {
        const long long* p = (const long long*)ei;
        src[i] = (int)p[i];
        dst[i] = (int)p[e + i];
    } else {
        const int* p = (const int*)ei;
        src[i] = p[i];
        dst[i] = p[e + i];
    }
}

// ---------------------------------------------------------------------------
// Degree + dinv
// ---------------------------------------------------------------------------
__global__ void zero_deg_kernel(int* deg, int n) {
    int i = blockIdx.x * blockDim.x + threadIdx.x;
    if (i < n) deg[i] = 0;
}
__global__ void count_deg_kernel(const int* __restrict__ dst, int* deg, int e) {
    int i = blockIdx.x * blockDim.x + threadIdx.x;
    if (i < e) atomicAdd(&deg[dst[i]], 1);
}
__global__ void dinv_kernel(const int* __restrict__ deg, float* dinv, int n) {
    int i = blockIdx.x * blockDim.x + threadIdx.x;
    if (i < n) dinv[i] = rsqrtf((float)(deg[i] + 1));  // +1 self loop
}

// ---------------------------------------------------------------------------
// 3-kernel exclusive prefix scan of deg -> rowptr
// ---------------------------------------------------------------------------
__global__ void scan1_kernel(const int* __restrict__ deg, int* rowptr, int* bsum, int n) {
    __shared__ int sm[SCAN_BLK];
    int i = blockIdx.x * SCAN_BLK + threadIdx.x;
    int v = (i < n) ? deg[i] : 0;
    sm[threadIdx.x] = v;
    __syncthreads();
    for (int o = 1; o < SCAN_BLK; o <<= 1) {
        int t = (threadIdx.x >= o) ? sm[threadIdx.x - o] : 0;
        __syncthreads();
        sm[threadIdx.x] += t;
        __syncthreads();
    }
    if (i < n) rowptr[i] = sm[threadIdx.x] - v;
    if (threadIdx.x == SCAN_BLK - 1) bsum[blockIdx.x] = sm[SCAN_BLK - 1];
}

__global__ void scan2_kernel(int* bsum, int nb) {
    __shared__ int sm[256];
    int v = (threadIdx.x < nb) ? bsum[threadIdx.x] : 0;
    sm[threadIdx.x] = v;
    __syncthreads();
    for (int o = 1; o < 256; o <<= 1) {
        int t = (threadIdx.x >= o) ? sm[threadIdx.x - o] : 0;
        __syncthreads();
        sm[threadIdx.x] += t;
        __syncthreads();
    }
    if (threadIdx.x < nb) bsum[threadIdx.x] = sm[threadIdx.x] - v;
}

__global__ void scan3_kernel(int* rowptr, const int* __restrict__ bsum, int* cursor, int n, int e) {
    int i = blockIdx.x * blockDim.x + threadIdx.x;
    if (i < n) {
        int r = rowptr[i] + bsum[i / SCAN_BLK];
        rowptr[i] = r;
        cursor[i] = r;
    }
    if (i == 0) rowptr[n] = e;
}

// ---------------------------------------------------------------------------
// CSR fill: slot = cursor[dst]++; store src and precomputed edge weight.
// ---------------------------------------------------------------------------
__global__ void fill_csr_kernel(const int* __restrict__ src, const int* __restrict__ dst,
                                const float* __restrict__ dinv, int* cursor,
                                int* __restrict__ csrc, float* __restrict__ cw, int e) {
    int i = blockIdx.x * blockDim.x + threadIdx.x;
    if (i >= e) return;
    int s = src[i];
    int d = dst[i];
    int pos = atomicAdd(&cursor[d], 1);
    csrc[pos] = s;
    cw[pos] = dinv[s] * dinv[d];
}

// ---------------------------------------------------------------------------
// GEMM: Y[M,NC] = X[M,K] @ W[K,NC] (+ bias). Smem-tiled, fp32.
// ---------------------------------------------------------------------------
template <int K, int NC, bool BIAS>
__global__ void gemm_kernel(const float* __restrict__ X, const float* __restrict__ W,
                            const float* __restrict__ bias, float* __restrict__ Y, int M) {
    constexpr int BR = 32;
    constexpr int NCH = NC / 2;
    constexpr int TY = 256 / NCH;
    constexpr int RPT = BR / TY;

    extern __shared__ float sm[];
    float* sW = sm;              // K * NC
    float* sX = sm + K * NC;     // K * (BR+1), [k][r]

    int tid = threadIdx.x;
    int base = blockIdx.x * BR;

    for (int i = tid; i < K * NC; i += 256) sW[i] = W[i];
    for (int i = tid; i < BR * K; i += 256) {
        int r = i / K, k = i % K;
        sX[k * (BR + 1) + r] = X[(size_t)(base + r) * K + k];
    }
    __syncthreads();

    int tx = tid % NCH;
    int ty = tid / NCH;

    float acc0[RPT], acc1[RPT];
#pragma unroll
    for (int r = 0; r < RPT; r++) { acc0[r] = 0.f; acc1[r] = 0.f; }

#pragma unroll 4
    for (int k = 0; k < K; k++) {
        float w0 = sW[k * NC + tx];
        float w1 = sW[k * NC + tx + NCH];
#pragma unroll
        for (int r = 0; r < RPT; r++) {
            float xv = sX[k * (BR + 1) + ty + r * TY];
            acc0[r] += xv * w0;
            acc1[r] += xv * w1;
        }
    }

#pragma unroll
    for (int r = 0; r < RPT; r++) {
        int row = base + ty + r * TY;
        float b0 = BIAS ? bias[tx] : 0.f;
        float b1 = BIAS ? bias[tx + NCH] : 0.f;
        Y[(size_t)row * NC + tx] = acc0[r] + b0;
        Y[(size_t)row * NC + tx + NCH] = acc1[r] + b1;
    }
}

// ---------------------------------------------------------------------------
// Fused aggregation: out[g] = (opt relu)( sum_{incoming} w*t[src] +
//                                         dinv[g]^2 * t[g] + bias )
//   F4 threads per node, one float4 lane each; 2-edge unrolled gather.
// ---------------------------------------------------------------------------
template <int F4, bool RELU>
__global__ void gather_kernel(const int* __restrict__ rowptr, const int* __restrict__ csrc,
                              const float* __restrict__ cw, const float4* __restrict__ t,
                              const float* __restrict__ dinv, const float4* __restrict__ bias,
                              float4* __restrict__ out, int n) {
    int g = blockIdx.x * (256 / F4) + threadIdx.x / F4;
    int lane = threadIdx.x % F4;
    if (g >= n) return;

    int start = rowptr[g];
    int end = rowptr[g + 1];
    float di = dinv[g];
    float s2 = di * di;

    float4 acc = t[(size_t)g * F4 + lane];
    float4 bb = bias[lane];
    acc.x = acc.x * s2 + bb.x;
    acc.y = acc.y * s2 + bb.y;
    acc.z = acc.z * s2 + bb.z;
    acc.w = acc.w * s2 + bb.w;

    int k = start;
    for (; k + 1 < end; k += 2) {
        int s0 = csrc[k], s1 = csrc[k + 1];
        float w0 = cw[k], w1 = cw[k + 1];
        float4 v0 = t[(size_t)s0 * F4 + lane];
        float4 v1 = t[(size_t)s1 * F4 + lane];
        acc.x += v0.x * w0 + v1.x * w1;
        acc.y += v0.y * w0 + v1.y * w1;
        acc.z += v0.z * w0 + v1.z * w1;
        acc.w += v0.w * w0 + v1.w * w1;
    }
    if (k < end) {
        int s0 = csrc[k];
        float w0 = cw[k];
        float4 v0 = t[(size_t)s0 * F4 + lane];
        acc.x += v0.x * w0;
        acc.y += v0.y * w0;
        acc.z += v0.z * w0;
        acc.w += v0.w * w0;
    }

    if (RELU) {
        acc.x = fmaxf(acc.x, 0.f);
        acc.y = fmaxf(acc.y, 0.f);
        acc.z = fmaxf(acc.z, 0.f);
        acc.w = fmaxf(acc.w, 0.f);
    }
    out[(size_t)g * F4 + lane] = acc;
}

// ---------------------------------------------------------------------------
// Final L2 row-normalize (32 features per node -> one warp per node)
// ---------------------------------------------------------------------------
__global__ void normalize_kernel(const float* __restrict__ a, float* __restrict__ out, int n) {
    int node = blockIdx.x * 8 + (threadIdx.x >> 5);
    int lane = threadIdx.x & 31;
    if (node >= n) return;
    float v = a[node * 32 + lane];
    float ss = v * v;
#pragma unroll
    for (int o = 16; o; o >>= 1) ss += __shfl_xor_sync(0xffffffffu, ss, o);
    float nrm = sqrtf(ss);
    out[node * 32 + lane] = v / fmaxf(nrm, 1e-12f);
}

// ---------------------------------------------------------------------------
extern "C" void kernel_launch(void* const* d_in, const int* in_sizes, int n_in,
                              void* d_out, int out_size) {
    const float* x = (const float*)d_in[0];
    const void* ei = d_in[1];
    const float* W_pre = (const float*)d_in[2];
    const float* b_pre = (const float*)d_in[3];
    const float* W1 = (const float*)d_in[4];
    const float* b1 = (const float*)d_in[5];
    const float* W2 = (const float*)d_in[6];
    const float* b2 = (const float*)d_in[7];
    const float* W3 = (const float*)d_in[8];
    const float* b3 = (const float*)d_in[9];
    float* out = (float*)d_out;

    const int n = NNODES;
    const int e = NEDGES;

    float *h, *t, *acc, *dinv, *cw;
    int *src, *dst, *is64, *deg, *rowptr, *cursor, *bsum, *csrc;
    cudaGetSymbolAddress((void**)&h, g_h);
    cudaGetSymbolAddress((void**)&t, g_t);
    cudaGetSymbolAddress((void**)&acc, g_acc);
    cudaGetSymbolAddress((void**)&dinv, g_dinv);
    cudaGetSymbolAddress((void**)&src, g_src);
    cudaGetSymbolAddress((void**)&dst, g_dst);
    cudaGetSymbolAddress((void**)&is64, g_is64);
    cudaGetSymbolAddress((void**)&deg, g_deg);
    cudaGetSymbolAddress((void**)&rowptr, g_rowptr);
    cudaGetSymbolAddress((void**)&cursor, g_cursor);
    cudaGetSymbolAddress((void**)&bsum, g_bsum);
    cudaGetSymbolAddress((void**)&csrc, g_csrc);
    cudaGetSymbolAddress((void**)&cw, g_cw);

    const int smem_pre = (128 * 64 + 128 * 33) * 4;   // 49664 > 48KB default
    const int smem_64 = (64 * 64 + 64 * 33) * 4;
    const int smem_32 = (64 * 32 + 64 * 33) * 4;
    cudaFuncSetAttribute(gemm_kernel<128, 64, true>,
                         cudaFuncAttributeMaxDynamicSharedMemorySize, smem_pre);

    // 0) detect dtype + normalize indices
    detect_idx_kernel<<<1, 256>>>((const unsigned*)ei, is64);
    convert_idx_kernel<<<(e + 255) / 256, 256>>>(ei, is64, src, dst, e);

    // 1) degree, dinv
    zero_deg_kernel<<<(n + 255) / 256, 256>>>(deg, n);
    count_deg_kernel<<<(e + 255) / 256, 256>>>(dst, deg, e);
    dinv_kernel<<<(n + 255) / 256, 256>>>(deg, dinv, n);

    // 2) CSR build: scan + fill (weights precomputed once)
    scan1_kernel<<<SCAN_NB, SCAN_BLK>>>(deg, rowptr, bsum, n);
    scan2_kernel<<<1, 256>>>(bsum, SCAN_NB);
    scan3_kernel<<<(n + 255) / 256, 256>>>(rowptr, bsum, cursor, n, e);
    fill_csr_kernel<<<(e + 255) / 256, 256>>>(src, dst, dinv, cursor, csrc, cw, e);

    // 3) h = x @ W_pre + b_pre
    gemm_kernel<128, 64, true><<<n / 32, 256, smem_pre>>>(x, W_pre, b_pre, h, n);

    // 4) layer 1: h = relu(aggregate(h @ W1) + b1)
    gemm_kernel<64, 64, false><<<n / 32, 256, smem_64>>>(h, W1, nullptr, t, n);
    gather_kernel<16, true><<<(n * 16 + 255) / 256, 256>>>(rowptr, csrc, cw, (const float4*)t,
                                                           dinv, (const float4*)b1, (float4*)h, n);

    // 5) layer 2
    gemm_kernel<64, 64, false><<<n / 32, 256, smem_64>>>(h, W2, nullptr, t, n);
    gather_kernel<16, true><<<(n * 16 + 255) / 256, 256>>>(rowptr, csrc, cw, (const float4*)t,
                                                           dinv, (const float4*)b2, (float4*)h, n);

    // 6) layer 3 (Fout=32, no relu)
    gemm_kernel<64, 32, false><<<n / 32, 256, smem_32>>>(h, W3, nullptr, t, n);
    gather_kernel<8, false><<<(n * 8 + 255) / 256, 256>>>(rowptr, csrc, cw, (const float4*)t,
                                                          dinv, (const float4*)b3, (float4*)acc, n);

    // 7) L2 normalize rows -> output
    normalize_kernel<<<(n + 7) / 8, 256>>>(acc, out, n);
}